// round 6
// baseline (speedup 1.0000x reference)
#include <cuda_runtime.h>
#include <cuda_bf16.h>

// Problem shape (FeatureGradFetcher): B=2, V=5, C=16, H=512, W=640, N=131072
#define BB 2
#define VV 5
#define CC 16
#define HH 512
#define WW 640
#define HW_ (HH * WW)          // 327680
#define NBV (BB * VV)          // 10

// Scratch: feature maps transposed to (bv, h, w, c) so one pixel's 16 channels
// are 64 contiguous, 64B-aligned bytes. ~210 MB, static __device__ (no allocs).
__device__ float g_fmT[(size_t)NBV * HW_ * CC];

// Streaming (evict-first) stores: data written once, not re-read soon.
__device__ __forceinline__ void st_cs(float* p, float v) {
    asm volatile("st.global.cs.f32 [%0], %1;" :: "l"(p), "f"(v) : "memory");
}
__device__ __forceinline__ void st_cs_v2(float2* p, float2 v) {
    asm volatile("st.global.cs.v2.f32 [%0], {%1, %2};" :: "l"(p), "f"(v.x), "f"(v.y) : "memory");
}
__device__ __forceinline__ void st_cs_v4(float4* p, float4 v) {
    asm volatile("st.global.cs.v4.f32 [%0], {%1, %2, %3, %4};"
                 :: "l"(p), "f"(v.x), "f"(v.y), "f"(v.z), "f"(v.w) : "memory");
}

// ---------------------------------------------------------------------------
// Kernel 1: transpose (bv, c, h, w) -> (bv, hw, c) via smem tiles.
// Block = 256 threads, tile = 64 pixels x 16 channels. DRAM-bound stream.
// ---------------------------------------------------------------------------
__global__ void __launch_bounds__(256) transpose_kernel(const float* __restrict__ fm) {
    __shared__ float tile[CC][64 + 1];

    const int bv   = blockIdx.y;
    const int pix0 = blockIdx.x * 64;
    const int tid  = threadIdx.x;

    const int pix = tid & 63;   // 0..63
    const int c0  = tid >> 6;   // 0..3

    const float* src = fm + (size_t)bv * CC * HW_ + pix0 + pix;
#pragma unroll
    for (int i = 0; i < 4; i++) {
        int c = i * 4 + c0;
        tile[c][pix] = __ldg(src + (size_t)c * HW_);
    }
    __syncthreads();

    float4* dst = (float4*)(g_fmT + ((size_t)bv * HW_ + pix0) * CC);
    const int p  = tid >> 2;        // pixel within tile, 0..63
    const int cw = (tid & 3) * 4;   // starting channel, {0,4,8,12}
    float4 v;
    v.x = tile[cw + 0][p];
    v.y = tile[cw + 1][p];
    v.z = tile[cw + 2][p];
    v.w = tile[cw + 3][p];
    st_cs_v4(dst + tid, v);
}

// ---------------------------------------------------------------------------
// Kernel 2: project + 5x bilinear sample + gradients.
// Lane mapping: 8 points x 4 channel-groups per warp (float4 loads; 4 lanes of
// a point share one 128B line). Fast path: the 5 sample footprints union to a
// 12-texel cross when floors align (99%+ of points); else 20-tap fallback.
// ---------------------------------------------------------------------------
__global__ void __launch_bounds__(256) sample_kernel(
    const float* __restrict__ pts,      // (B, 3, N)
    const float* __restrict__ Kall,     // (B, V, 3, 3)
    const float* __restrict__ Eall,     // (B, V, 3, 4)
    float* __restrict__ out,            // f (BV,C,N) then f_grad (BV,C,N,2)
    int Npts)
{
    const int bv        = blockIdx.y;
    const int lane      = threadIdx.x & 31;
    const int warpInBlk = threadIdx.x >> 5;
    const int cg        = lane >> 3;                      // channel group 0..3
    const int n         = blockIdx.x * 64 + warpInBlk * 8 + (lane & 7);
    if (n >= Npts) return;

    const int b = bv / VV;

    // --- geometry ---
    const float* E = Eall + bv * 12;   // row-major 3x4
    const float* K = Kall + bv * 9;    // row-major 3x3
    const size_t pb = (size_t)b * 3 * Npts + n;
    const float px = __ldg(pts + pb);
    const float py = __ldg(pts + pb + Npts);
    const float pz = __ldg(pts + pb + 2 * (size_t)Npts);

    const float tx = fmaf(__ldg(E + 0), px, fmaf(__ldg(E + 1), py, fmaf(__ldg(E + 2),  pz, __ldg(E + 3))));
    const float ty = fmaf(__ldg(E + 4), px, fmaf(__ldg(E + 5), py, fmaf(__ldg(E + 6),  pz, __ldg(E + 7))));
    const float tz = fmaf(__ldg(E + 8), px, fmaf(__ldg(E + 9), py, fmaf(__ldg(E + 10), pz, __ldg(E + 11))));

    const float rz = 1.0f / tz;
    const float nx = tx * rz;
    const float ny = ty * rz;
    const float u  = fmaf(__ldg(K + 0), nx, fmaf(__ldg(K + 1), ny, __ldg(K + 2)));
    const float v  = fmaf(__ldg(K + 3), nx, fmaf(__ldg(K + 4), ny, __ldg(K + 5)));

    const float gx = (u - 0.5f) / (float)(WW - 1) * 2.0f - 1.0f;
    const float gy = (v - 0.5f) / (float)(HH - 1) * 2.0f - 1.0f;
    const float dx = 2.0f / (float)(WW - 1);
    const float dy = 2.0f / (float)(HH - 1);

    // Center sample pixel coords
    const float ix = ((gx + 1.0f) * (float)WW - 1.0f) * 0.5f;
    const float iy = ((gy + 1.0f) * (float)HH - 1.0f) * 0.5f;
    const float x0f = floorf(ix);
    const float y0f = floorf(iy);
    const float fx = ix - x0f;
    const float fy = iy - y0f;
    const int x0 = (int)x0f;
    const int y0 = (int)y0f;

    // Neighbor samples shift by W/(W-1) = 1 + ex pixels (NOT exactly 1).
    const float ex = 1.0f / (float)(WW - 1);
    const float ey = 1.0f / (float)(HH - 1);

    const float* fb = g_fmT + (size_t)bv * HW_ * CC + cg * 4;

    float fC[4], fL[4], fR[4], fT[4], fB4[4];

    const bool fast =
        (fx >= ex) && (fx < 1.0f - ex) &&
        (fy >= ey) && (fy < 1.0f - ey) &&
        (x0 >= 1) && (x0 <= WW - 3) && (y0 >= 1) && (y0 <= HH - 3);

    if (fast) {
        // 12-texel cross: rows y0-1..y0+2, cols x0-1..x0+2, minus the 4 corners.
        // Neighbor fractional weights: fx_l = fx-ex, fx_r = fx+ex, etc.
        const float fxl = fx - ex, fxr = fx + ex;
        const float fyt = fy - ey, fyb = fy + ey;

        const size_t rowStride = (size_t)WW * CC;
        const float* base = fb + ((size_t)y0 * WW + x0) * CC;   // texel (x0, y0)

        const float4 A  = __ldg((const float4*)(base - rowStride));            // (x0,  y0-1)
        const float4 Bx = __ldg((const float4*)(base - rowStride + CC));       // (x0+1,y0-1)
        const float4 Cx = __ldg((const float4*)(base - CC));                   // (x0-1,y0)
        const float4 D  = __ldg((const float4*)(base));                        // (x0,  y0)
        const float4 Ex = __ldg((const float4*)(base + CC));                   // (x0+1,y0)
        const float4 F  = __ldg((const float4*)(base + 2 * CC));               // (x0+2,y0)
        const float4 G  = __ldg((const float4*)(base + rowStride - CC));       // (x0-1,y0+1)
        const float4 Hx = __ldg((const float4*)(base + rowStride));            // (x0,  y0+1)
        const float4 I  = __ldg((const float4*)(base + rowStride + CC));       // (x0+1,y0+1)
        const float4 J  = __ldg((const float4*)(base + rowStride + 2 * CC));   // (x0+2,y0+1)
        const float4 K2 = __ldg((const float4*)(base + 2 * rowStride));        // (x0,  y0+2)
        const float4 L  = __ldg((const float4*)(base + 2 * rowStride + CC));   // (x0+1,y0+2)

        const float a_[4]  = {A.x, A.y, A.z, A.w};
        const float b_[4]  = {Bx.x, Bx.y, Bx.z, Bx.w};
        const float c_[4]  = {Cx.x, Cx.y, Cx.z, Cx.w};
        const float d_[4]  = {D.x, D.y, D.z, D.w};
        const float e_[4]  = {Ex.x, Ex.y, Ex.z, Ex.w};
        const float f_[4]  = {F.x, F.y, F.z, F.w};
        const float g_[4]  = {G.x, G.y, G.z, G.w};
        const float h_[4]  = {Hx.x, Hx.y, Hx.z, Hx.w};
        const float i_[4]  = {I.x, I.y, I.z, I.w};
        const float j_[4]  = {J.x, J.y, J.z, J.w};
        const float k_[4]  = {K2.x, K2.y, K2.z, K2.w};
        const float l_[4]  = {L.x, L.y, L.z, L.w};

#pragma unroll
        for (int k = 0; k < 4; k++) {
            // rows y0 / y0+1 horizontal lerps at three weight sets
            const float rowC_c = fmaf(fx,  e_[k] - d_[k], d_[k]);  // center cols (x0,x0+1) @ y0
            const float rowC_n = fmaf(fx,  i_[k] - h_[k], h_[k]);  // center cols @ y0+1
            fC[k]  = fmaf(fy, rowC_n - rowC_c, rowC_c);

            const float rowL_c = fmaf(fxl, d_[k] - c_[k], c_[k]);  // cols (x0-1,x0) @ y0
            const float rowL_n = fmaf(fxl, h_[k] - g_[k], g_[k]);
            fL[k]  = fmaf(fy, rowL_n - rowL_c, rowL_c);

            const float rowR_c = fmaf(fxr, f_[k] - e_[k], e_[k]);  // cols (x0+1,x0+2) @ y0
            const float rowR_n = fmaf(fxr, j_[k] - i_[k], i_[k]);
            fR[k]  = fmaf(fy, rowR_n - rowR_c, rowR_c);

            const float rowT   = fmaf(fx,  b_[k] - a_[k], a_[k]);  // center cols @ y0-1
            fT[k]  = fmaf(fyt, rowC_c - rowT, rowT);

            const float rowB   = fmaf(fx,  l_[k] - k_[k], k_[k]);  // center cols @ y0+2
            fB4[k] = fmaf(fyb, rowB - rowC_n, rowC_n);
        }
    } else {
        // Fallback: 5 independent bilinear samples with bounds checks.
        const float gxs[5] = {gx, gx - dx, gx + dx, gx,      gx     };
        const float gys[5] = {gy, gy,      gy,      gy - dy, gy + dy};
        float acc[5][4];
#pragma unroll
        for (int s = 0; s < 5; s++)
#pragma unroll
            for (int k = 0; k < 4; k++) acc[s][k] = 0.0f;

#pragma unroll
        for (int s = 0; s < 5; s++) {
            const float ixs = ((gxs[s] + 1.0f) * (float)WW - 1.0f) * 0.5f;
            const float iys = ((gys[s] + 1.0f) * (float)HH - 1.0f) * 0.5f;
            const float sx0f = floorf(ixs);
            const float sy0f = floorf(iys);
            const float wx1 = ixs - sx0f;
            const float wy1 = iys - sy0f;
            const float wx0 = 1.0f - wx1;
            const float wy0 = 1.0f - wy1;
            const int sx0 = (int)sx0f;
            const int sy0 = (int)sy0f;

            const int   xs[2]  = {sx0, sx0 + 1};
            const int   ys[2]  = {sy0, sy0 + 1};
            const float wxs[2] = {wx0, wx1};
            const float wys[2] = {wy0, wy1};

#pragma unroll
            for (int tyi = 0; tyi < 2; tyi++) {
#pragma unroll
                for (int txi = 0; txi < 2; txi++) {
                    const int xi = xs[txi];
                    const int yi = ys[tyi];
                    if (xi >= 0 && xi < WW && yi >= 0 && yi < HH) {
                        const float w = wxs[txi] * wys[tyi];
                        const float4 d =
                            __ldg((const float4*)(fb + ((size_t)yi * WW + xi) * CC));
                        acc[s][0] = fmaf(w, d.x, acc[s][0]);
                        acc[s][1] = fmaf(w, d.y, acc[s][1]);
                        acc[s][2] = fmaf(w, d.z, acc[s][2]);
                        acc[s][3] = fmaf(w, d.w, acc[s][3]);
                    }
                }
            }
        }
#pragma unroll
        for (int k = 0; k < 4; k++) {
            fC[k] = acc[0][k]; fL[k] = acc[1][k]; fR[k] = acc[2][k];
            fT[k] = acc[3][k]; fB4[k] = acc[4][k];
        }
    }

    // --- outputs (streaming stores: never re-read) ---
    // f: (BV, C, N), this lane covers channels cg*4 .. cg*4+3
    float* outF = out;
    const size_t f0 = ((size_t)bv * CC + cg * 4) * Npts + n;
    st_cs(outF + f0,                    fC[0]);
    st_cs(outF + f0 + (size_t)Npts,     fC[1]);
    st_cs(outF + f0 + 2 * (size_t)Npts, fC[2]);
    st_cs(outF + f0 + 3 * (size_t)Npts, fC[3]);

    // f_grad: (BV, C, N, 2) — (gx,gy) pair per (c,n)
    float2* outG = (float2*)(out + (size_t)NBV * CC * Npts);
#pragma unroll
    for (int k = 0; k < 4; k++) {
        const size_t gi = ((size_t)bv * CC + cg * 4 + k) * Npts + n;
        float2 g;
        g.x = 0.5f * (fR[k] - fL[k]);
        g.y = 0.5f * (fB4[k] - fT[k]);
        st_cs_v2(outG + gi, g);
    }
}

// ---------------------------------------------------------------------------
// Launch: transpose once, then sample. Both graph-capturable, no allocations.
// Inputs resolved by SIZE fingerprint (robust to metadata ordering):
//   fm = B*V*C*H*W = 52,428,800   pts = B*3*N = 786,432
//   K  = B*V*9     = 90           E   = B*V*12 = 120
// ---------------------------------------------------------------------------
extern "C" void kernel_launch(void* const* d_in, const int* in_sizes, int n_in,
                              void* d_out, int out_size) {
    const float* fm  = nullptr;
    const float* pts = nullptr;
    const float* K   = nullptr;
    const float* E   = nullptr;
    int pts_size = 0;

    for (int i = 0; i < n_in; i++) {
        const int s = in_sizes[i];
        if (s == NBV * 9) {
            K = (const float*)d_in[i];
        } else if (s == NBV * 12) {
            E = (const float*)d_in[i];
        } else if (s == (int)((size_t)NBV * CC * HW_)) {
            fm = (const float*)d_in[i];
        } else {
            pts = (const float*)d_in[i];
            pts_size = s;
        }
    }
    // Fallback to positional binding if fingerprinting failed.
    if (!fm || !pts || !K || !E) {
        fm  = (const float*)d_in[0];
        pts = (const float*)d_in[1];
        K   = (const float*)d_in[2];
        E   = (const float*)d_in[3];
        pts_size = in_sizes[1];
    }

    float* out = (float*)d_out;
    const int Npts = pts_size / (BB * 3);   // pts is (B, 3, N)

    dim3 tgrid(HW_ / 64, NBV);
    transpose_kernel<<<tgrid, 256>>>(fm);

    dim3 sgrid((Npts + 63) / 64, NBV);
    sample_kernel<<<sgrid, 256>>>(pts, K, E, out, Npts);
}